// round 1
// baseline (speedup 1.0000x reference)
#include <cuda_runtime.h>

#define LENGTH_MAX 200000
#define RANK 64
#define WIN 11
#define PAD 5
#define TILE 64
#define THREADS 256
#define NWARPS 8
#define RPW 8   // rows per warp

// Shared layout:
//  Wt2[k*32 + c] = ( W[c][k], W[c+32][k] )  -> lane c reads its two output cols
//  xt[(TILE+2*PAD)][RANK]                   -> padded row tile (zeros outside)
__global__ void __launch_bounds__(THREADS) attn_window_kernel(
    const float* __restrict__ X,   // (L, 64)
    const float* __restrict__ W,   // (64, 64) row-major (out, in)
    const float* __restrict__ b,   // (64,)
    float* __restrict__ out,       // (L, 64)
    int length)
{
    __shared__ float2 Wt2[RANK * 32];
    __shared__ float  xt[(TILE + 2 * PAD) * RANK];

    const int tid  = threadIdx.x;
    const int lane = tid & 31;
    const int wid  = tid >> 5;
    const int tile_start = blockIdx.x * TILE;

    // ---- load W transposed+interleaved into shared ----
    for (int i = tid; i < RANK * 32; i += THREADS) {
        int k = i >> 5;
        int c = i & 31;
        Wt2[i] = make_float2(W[c * RANK + k], W[(c + 32) * RANK + k]);
    }
    // ---- load padded X tile (rows tile_start-PAD .. tile_start+TILE+PAD) ----
    for (int i = tid; i < (TILE + 2 * PAD) * (RANK / 4); i += THREADS) {
        int lr = i / (RANK / 4);
        int cc = (i % (RANK / 4)) * 4;
        int gr = tile_start - PAD + lr;
        float4 v = make_float4(0.f, 0.f, 0.f, 0.f);
        if (gr >= 0 && gr < length)
            v = *reinterpret_cast<const float4*>(&X[(size_t)gr * RANK + cc]);
        *reinterpret_cast<float4*>(&xt[lr * RANK + cc]) = v;
    }
    __syncthreads();

    const float b0 = b[lane];
    const float b1 = b[lane + 32];

    const int base_lr = wid * RPW;   // this warp's 8 rows within the tile

    // ---- var1 = tanh(X W^T + b) for 8 rows at once (amortize W LDS) ----
    float a0[RPW], a1[RPW];
    #pragma unroll
    for (int r = 0; r < RPW; r++) { a0[r] = b0; a1[r] = b1; }

    #pragma unroll 4
    for (int k4 = 0; k4 < RANK; k4 += 4) {
        float2 w0 = Wt2[(k4 + 0) * 32 + lane];
        float2 w1 = Wt2[(k4 + 1) * 32 + lane];
        float2 w2 = Wt2[(k4 + 2) * 32 + lane];
        float2 w3 = Wt2[(k4 + 3) * 32 + lane];
        #pragma unroll
        for (int r = 0; r < RPW; r++) {
            float4 xv = *reinterpret_cast<const float4*>(
                &xt[(base_lr + r + PAD) * RANK + k4]);
            a0[r] = fmaf(xv.x, w0.x, a0[r]); a1[r] = fmaf(xv.x, w0.y, a1[r]);
            a0[r] = fmaf(xv.y, w1.x, a0[r]); a1[r] = fmaf(xv.y, w1.y, a1[r]);
            a0[r] = fmaf(xv.z, w2.x, a0[r]); a1[r] = fmaf(xv.z, w2.y, a1[r]);
            a0[r] = fmaf(xv.w, w3.x, a0[r]); a1[r] = fmaf(xv.w, w3.y, a1[r]);
        }
    }
    #pragma unroll
    for (int r = 0; r < RPW; r++) { a0[r] = tanhf(a0[r]); a1[r] = tanhf(a1[r]); }

    // ---- per row: window scores -> softmax -> weighted sum ----
    #pragma unroll
    for (int r = 0; r < RPW; r++) {
        const int lr = base_lr + r;
        const int gr = tile_start + lr;
        if (gr >= length) break;

        float p[WIN];
        #pragma unroll
        for (int w = 0; w < WIN; w++) {
            const float* br = &xt[(lr + w) * RANK];
            p[w] = br[lane] * a0[r] + br[lane + 32] * a1[r];
        }
        // butterfly reduce across the warp (full 64-dim dot: 2 cols/lane)
        #pragma unroll
        for (int off = 16; off > 0; off >>= 1) {
            #pragma unroll
            for (int w = 0; w < WIN; w++)
                p[w] += __shfl_xor_sync(0xffffffffu, p[w], off);
        }
        // stable softmax over window (scores scaled by 1/sqrt(64) = 1/8)
        float m = p[0];
        #pragma unroll
        for (int w = 1; w < WIN; w++) m = fmaxf(m, p[w]);
        float sum = 0.f;
        #pragma unroll
        for (int w = 0; w < WIN; w++) {
            p[w] = __expf((p[w] - m) * 0.125f);
            sum += p[w];
        }
        const float inv = 1.0f / sum;

        float o0 = 0.f, o1 = 0.f;
        #pragma unroll
        for (int w = 0; w < WIN; w++) {
            const float* br = &xt[(lr + w) * RANK];
            const float s = p[w] * inv;
            o0 = fmaf(s, br[lane], o0);
            o1 = fmaf(s, br[lane + 32], o1);
        }
        out[(size_t)gr * RANK + lane]      = o0;
        out[(size_t)gr * RANK + lane + 32] = o1;
    }
}

extern "C" void kernel_launch(void* const* d_in, const int* in_sizes, int n_in,
                              void* d_out, int out_size)
{
    const float* X = (const float*)d_in[0];   // time_factor (L, 64)
    const float* W = (const float*)d_in[1];   // (64, 64)
    const float* b = (const float*)d_in[2];   // (64,)
    float* out = (float*)d_out;

    const int length = in_sizes[0] / RANK;
    const int grid = (length + TILE - 1) / TILE;
    attn_window_kernel<<<grid, THREADS>>>(X, W, b, out, length);
}

// round 2
// speedup vs baseline: 1.1317x; 1.1317x over previous
#include <cuda_runtime.h>

#define RANK    64
#define WIN     11
#define PAD     5
#define TILE    64
#define THREADS 256
#define NWARPS  8
#define RPW     8      // rows per warp
#define XSTR    68     // padded row stride (floats) for xt and v1 (272B, 16B-aligned)

// Packed fp32x2 FMA (Blackwell FFMA2) — only reachable via PTX.
#define FMA2(d, a, b, c) \
    asm("fma.rn.f32x2 %0, %1, %2, %3;" : "=l"(d) : "l"(a), "l"(b), "l"(c))

__device__ __forceinline__ float2 unpack2(unsigned long long v) {
    float2 r;
    asm("mov.b64 {%0, %1}, %2;" : "=f"(r.x), "=f"(r.y) : "l"(v));
    return r;
}

// tanh(x) = 1 - 2/(e^(2x)+1). MUFU-based, rel err ~1e-5 (tolerance is 1e-3).
__device__ __forceinline__ float fast_tanh(float x) {
    float e = __expf(2.0f * x);
    return 1.0f - __fdividef(2.0f, e + 1.0f);
}

__global__ void __launch_bounds__(THREADS) attn_window_kernel(
    const float* __restrict__ X,   // (L, 64)
    const float* __restrict__ W,   // (64, 64) row-major (out, in)
    const float* __restrict__ b,   // (64,)
    float* __restrict__ out,       // (L, 64)
    int length)
{
    // ubuf: first holds W in k-paired layout (16KB), later reused for v1 (64 x XSTR)
    __shared__ __align__(16) float ubuf[TILE * XSTR];               // 4352 floats = 17.4KB
    __shared__ __align__(16) float xt[(TILE + 2 * PAD) * XSTR];     // 74 x 68 = 20.1KB
    __shared__ float sc[NWARPS][RPW][12];                           // scores scratch, 3KB

    const int tid  = threadIdx.x;
    const int lane = tid & 31;
    const int wid  = tid >> 5;
    const int tile_start = blockIdx.x * TILE;
    const int base_lr = wid * RPW;

    // ---- load W in k-paired layout: wbuf[kp*32 + c] = (W[c][2kp], W[c][2kp+1]) ----
    {
        const float2* Wg = (const float2*)W;
        float2* wbuf = (float2*)ubuf;   // [0..1023] cols 0-31, [1024..2047] cols 32-63
        for (int i = tid; i < 2048; i += THREADS) {
            int c  = i >> 5;     // 0..63
            int kp = i & 31;     // k-pair index
            float2 v = Wg[c * 32 + kp];
            wbuf[(c < 32 ? 0 : 1024) + kp * 32 + (c & 31)] = v;
        }
    }
    // ---- load padded X tile (rows tile_start-PAD .. +TILE+PAD), stride XSTR ----
    for (int i = tid; i < (TILE + 2 * PAD) * (RANK / 4); i += THREADS) {
        int lr = i >> 4;
        int cc = (i & 15) << 2;
        int gr = tile_start - PAD + lr;
        float4 v = make_float4(0.f, 0.f, 0.f, 0.f);
        if (gr >= 0 && gr < length)
            v = *reinterpret_cast<const float4*>(&X[(size_t)gr * RANK + cc]);
        *reinterpret_cast<float4*>(&xt[lr * XSTR + cc]) = v;
    }
    __syncthreads();

    // ---- Phase A: var1 = tanh(X W^T + b), packed f32x2 over k (split accumulators) ----
    unsigned long long acc0[RPW], acc1[RPW];
    #pragma unroll
    for (int r = 0; r < RPW; r++) { acc0[r] = 0ull; acc1[r] = 0ull; }

    const unsigned long long* w0u = (const unsigned long long*)ubuf;
    const unsigned long long* w1u = w0u + 1024;

    #pragma unroll 4
    for (int kq = 0; kq < 16; kq++) {   // covers k = 4kq .. 4kq+3
        unsigned long long wa0 = w0u[(2 * kq)     * 32 + lane];
        unsigned long long wb0 = w0u[(2 * kq + 1) * 32 + lane];
        unsigned long long wa1 = w1u[(2 * kq)     * 32 + lane];
        unsigned long long wb1 = w1u[(2 * kq + 1) * 32 + lane];
        #pragma unroll
        for (int r = 0; r < RPW; r++) {
            ulonglong2 xv = *reinterpret_cast<const ulonglong2*>(
                &xt[(base_lr + r + PAD) * XSTR + 4 * kq]);
            FMA2(acc0[r], xv.x, wa0, acc0[r]);
            FMA2(acc1[r], xv.x, wa1, acc1[r]);
            FMA2(acc0[r], xv.y, wb0, acc0[r]);
            FMA2(acc1[r], xv.y, wb1, acc1[r]);
        }
    }

    __syncthreads();   // all warps done reading W before v1 overlays it

    float* v1s = ubuf;   // v1[row][c], stride XSTR
    {
        const float b0 = b[lane];
        const float b1 = b[lane + 32];
        #pragma unroll
        for (int r = 0; r < RPW; r++) {
            float2 u0 = unpack2(acc0[r]);
            float2 u1 = unpack2(acc1[r]);
            v1s[(base_lr + r) * XSTR + lane]      = fast_tanh(u0.x + u0.y + b0);
            v1s[(base_lr + r) * XSTR + lane + 32] = fast_tanh(u1.x + u1.y + b1);
        }
    }
    __syncwarp();

    // ---- scores: 88 (row,window) dots per warp, one full dot per lane, no shuffles ----
    #pragma unroll
    for (int p = 0; p < 3; p++) {
        int d = p * 32 + lane;
        if (d < RPW * WIN) {
            int r8 = d / 11;
            int w  = d - r8 * 11;
            const ulonglong2* vp = (const ulonglong2*)&v1s[(base_lr + r8) * XSTR];
            const ulonglong2* xp = (const ulonglong2*)&xt[(base_lr + r8 + w) * XSTR];
            unsigned long long s0 = 0ull, s1 = 0ull;
            #pragma unroll
            for (int kq = 0; kq < 16; kq++) {
                ulonglong2 a  = vp[kq];
                ulonglong2 x2 = xp[kq];
                FMA2(s0, a.x, x2.x, s0);
                FMA2(s1, a.y, x2.y, s1);
            }
            float2 f0 = unpack2(s0), f1 = unpack2(s1);
            sc[wid][r8][w] = f0.x + f0.y + f1.x + f1.y;
        }
    }
    __syncwarp();

    // ---- softmax over window (8 lanes, one row each), scale 1/sqrt(64)=1/8 ----
    if (lane < RPW) {
        float pb[WIN];
        float m = -1e30f;
        #pragma unroll
        for (int w = 0; w < WIN; w++) { pb[w] = sc[wid][lane][w]; m = fmaxf(m, pb[w]); }
        float s = 0.f;
        #pragma unroll
        for (int w = 0; w < WIN; w++) { pb[w] = __expf((pb[w] - m) * 0.125f); s += pb[w]; }
        float inv = 1.0f / s;
        #pragma unroll
        for (int w = 0; w < WIN; w++) sc[wid][lane][w] = pb[w] * inv;
    }
    __syncwarp();

    // ---- output: transposed accumulation — each of the 18 x-rows loaded once ----
    float2 o[RPW];
    #pragma unroll
    for (int r = 0; r < RPW; r++) o[r] = make_float2(0.f, 0.f);

    #pragma unroll
    for (int t = 0; t < RPW + WIN - 1; t++) {   // 18 shared rows per warp
        float2 xv = *reinterpret_cast<const float2*>(
            &xt[(base_lr + t) * XSTR + 2 * lane]);
        #pragma unroll
        for (int r = 0; r < RPW; r++) {
            const int w = t - r;
            if (w >= 0 && w < WIN) {
                float s = sc[wid][r][w];     // smem broadcast
                o[r].x = fmaf(s, xv.x, o[r].x);
                o[r].y = fmaf(s, xv.y, o[r].y);
            }
        }
    }
    #pragma unroll
    for (int r = 0; r < RPW; r++) {
        int gr = tile_start + base_lr + r;
        if (gr < length)
            *reinterpret_cast<float2*>(&out[(size_t)gr * RANK + 2 * lane]) = o[r];
    }
}

extern "C" void kernel_launch(void* const* d_in, const int* in_sizes, int n_in,
                              void* d_out, int out_size)
{
    const float* X = (const float*)d_in[0];   // time_factor (L, 64)
    const float* W = (const float*)d_in[1];   // (64, 64)
    const float* b = (const float*)d_in[2];   // (64,)
    float* out = (float*)d_out;

    const int length = in_sizes[0] / RANK;
    const int grid = (length + TILE - 1) / TILE;
    attn_window_kernel<<<grid, THREADS>>>(X, W, b, out, length);
}

// round 3
// speedup vs baseline: 1.1365x; 1.0042x over previous
#include <cuda_runtime.h>

#define RANK    64
#define WIN     11
#define PAD     5
#define TILE    64
#define THREADS 256
#define NWARPS  8
#define RPW     8      // rows per warp
#define XSTR    68     // padded row stride (floats) for xt and v1 (272B, 16B-aligned)

// Packed fp32x2 FMA (Blackwell FFMA2) — only reachable via PTX.
#define FMA2(d, a, b, c) \
    asm("fma.rn.f32x2 %0, %1, %2, %3;" : "=l"(d) : "l"(a), "l"(b), "l"(c))

__device__ __forceinline__ float2 unpack2(unsigned long long v) {
    float2 r;
    asm("mov.b64 {%0, %1}, %2;" : "=f"(r.x), "=f"(r.y) : "l"(v));
    return r;
}

// tanh(x) = 1 - 2/(e^(2x)+1). MUFU-based, rel err ~1e-5 (tolerance is 1e-3).
__device__ __forceinline__ float fast_tanh(float x) {
    float e = __expf(2.0f * x);
    return 1.0f - __fdividef(2.0f, e + 1.0f);
}

__global__ void __launch_bounds__(THREADS) attn_window_kernel(
    const float* __restrict__ X,   // (L, 64)
    const float* __restrict__ W,   // (64, 64) row-major (out, in)
    const float* __restrict__ b,   // (64,)
    float* __restrict__ out,       // (L, 64)
    int length)
{
    // ubuf: first holds W in k-paired layout (16KB), later reused for v1 (64 x XSTR)
    __shared__ __align__(16) float ubuf[TILE * XSTR];               // 4352 floats = 17.4KB
    __shared__ __align__(16) float xt[(TILE + 2 * PAD) * XSTR];     // 74 x 68 = 20.1KB
    __shared__ float sc[NWARPS][RPW][12];                           // scores scratch, 3KB

    const int tid  = threadIdx.x;
    const int lane = tid & 31;
    const int wid  = tid >> 5;
    const int tile_start = blockIdx.x * TILE;
    const int base_lr = wid * RPW;

    // ---- load W in k-paired layout: wbuf[kp*32 + c] = (W[c][2kp], W[c][2kp+1]) ----
    {
        const float2* Wg = (const float2*)W;
        float2* wbuf = (float2*)ubuf;   // [0..1023] cols 0-31, [1024..2047] cols 32-63
        for (int i = tid; i < 2048; i += THREADS) {
            int c  = i >> 5;     // 0..63
            int kp = i & 31;     // k-pair index
            float2 v = Wg[c * 32 + kp];
            wbuf[(c < 32 ? 0 : 1024) + kp * 32 + (c & 31)] = v;
        }
    }
    // ---- load padded X tile (rows tile_start-PAD .. +TILE+PAD), stride XSTR ----
    for (int i = tid; i < (TILE + 2 * PAD) * (RANK / 4); i += THREADS) {
        int lr = i >> 4;
        int cc = (i & 15) << 2;
        int gr = tile_start - PAD + lr;
        float4 v = make_float4(0.f, 0.f, 0.f, 0.f);
        if (gr >= 0 && gr < length)
            v = *reinterpret_cast<const float4*>(&X[(size_t)gr * RANK + cc]);
        *reinterpret_cast<float4*>(&xt[lr * XSTR + cc]) = v;
    }
    __syncthreads();

    // ---- Phase A: var1 = tanh(X W^T + b), packed f32x2 over k (split accumulators) ----
    unsigned long long acc0[RPW], acc1[RPW];
    #pragma unroll
    for (int r = 0; r < RPW; r++) { acc0[r] = 0ull; acc1[r] = 0ull; }

    const unsigned long long* w0u = (const unsigned long long*)ubuf;
    const unsigned long long* w1u = w0u + 1024;

    #pragma unroll 4
    for (int kq = 0; kq < 16; kq++) {   // covers k = 4kq .. 4kq+3
        unsigned long long wa0 = w0u[(2 * kq)     * 32 + lane];
        unsigned long long wb0 = w0u[(2 * kq + 1) * 32 + lane];
        unsigned long long wa1 = w1u[(2 * kq)     * 32 + lane];
        unsigned long long wb1 = w1u[(2 * kq + 1) * 32 + lane];
        #pragma unroll
        for (int r = 0; r < RPW; r++) {
            ulonglong2 xv = *reinterpret_cast<const ulonglong2*>(
                &xt[(base_lr + r + PAD) * XSTR + 4 * kq]);
            FMA2(acc0[r], xv.x, wa0, acc0[r]);
            FMA2(acc1[r], xv.x, wa1, acc1[r]);
            FMA2(acc0[r], xv.y, wb0, acc0[r]);
            FMA2(acc1[r], xv.y, wb1, acc1[r]);
        }
    }

    __syncthreads();   // all warps done reading W before v1 overlays it

    float* v1s = ubuf;   // v1[row][c], stride XSTR
    {
        const float b0 = b[lane];
        const float b1 = b[lane + 32];
        #pragma unroll
        for (int r = 0; r < RPW; r++) {
            float2 u0 = unpack2(acc0[r]);
            float2 u1 = unpack2(acc1[r]);
            v1s[(base_lr + r) * XSTR + lane]      = fast_tanh(u0.x + u0.y + b0);
            v1s[(base_lr + r) * XSTR + lane + 32] = fast_tanh(u1.x + u1.y + b1);
        }
    }
    __syncwarp();

    // ---- scores: 88 (row,window) dots per warp, one full dot per lane, no shuffles ----
    #pragma unroll
    for (int p = 0; p < 3; p++) {
        int d = p * 32 + lane;
        if (d < RPW * WIN) {
            int r8 = d / 11;
            int w  = d - r8 * 11;
            const ulonglong2* vp = (const ulonglong2*)&v1s[(base_lr + r8) * XSTR];
            const ulonglong2* xp = (const ulonglong2*)&xt[(base_lr + r8 + w) * XSTR];
            unsigned long long s0 = 0ull, s1 = 0ull;
            #pragma unroll
            for (int kq = 0; kq < 16; kq++) {
                ulonglong2 a  = vp[kq];
                ulonglong2 x2 = xp[kq];
                FMA2(s0, a.x, x2.x, s0);
                FMA2(s1, a.y, x2.y, s1);
            }
            float2 f0 = unpack2(s0), f1 = unpack2(s1);
            sc[wid][r8][w] = f0.x + f0.y + f1.x + f1.y;
        }
    }
    __syncwarp();

    // ---- softmax over window (8 lanes, one row each), scale 1/sqrt(64)=1/8 ----
    if (lane < RPW) {
        float pb[WIN];
        float m = -1e30f;
        #pragma unroll
        for (int w = 0; w < WIN; w++) { pb[w] = sc[wid][lane][w]; m = fmaxf(m, pb[w]); }
        float s = 0.f;
        #pragma unroll
        for (int w = 0; w < WIN; w++) { pb[w] = __expf((pb[w] - m) * 0.125f); s += pb[w]; }
        float inv = 1.0f / s;
        #pragma unroll
        for (int w = 0; w < WIN; w++) sc[wid][lane][w] = pb[w] * inv;
    }
    __syncwarp();

    // ---- output: transposed accumulation — each of the 18 x-rows loaded once ----
    float2 o[RPW];
    #pragma unroll
    for (int r = 0; r < RPW; r++) o[r] = make_float2(0.f, 0.f);

    #pragma unroll
    for (int t = 0; t < RPW + WIN - 1; t++) {   // 18 shared rows per warp
        float2 xv = *reinterpret_cast<const float2*>(
            &xt[(base_lr + t) * XSTR + 2 * lane]);
        #pragma unroll
        for (int r = 0; r < RPW; r++) {
            const int w = t - r;
            if (w >= 0 && w < WIN) {
                float s = sc[wid][r][w];     // smem broadcast
                o[r].x = fmaf(s, xv.x, o[r].x);
                o[r].y = fmaf(s, xv.y, o[r].y);
            }
        }
    }
    #pragma unroll
    for (int r = 0; r < RPW; r++) {
        int gr = tile_start + base_lr + r;
        if (gr < length)
            *reinterpret_cast<float2*>(&out[(size_t)gr * RANK + 2 * lane]) = o[r];
    }
}

extern "C" void kernel_launch(void* const* d_in, const int* in_sizes, int n_in,
                              void* d_out, int out_size)
{
    const float* X = (const float*)d_in[0];   // time_factor (L, 64)
    const float* W = (const float*)d_in[1];   // (64, 64)
    const float* b = (const float*)d_in[2];   // (64,)
    float* out = (float*)d_out;

    const int length = in_sizes[0] / RANK;
    const int grid = (length + TILE - 1) / TILE;
    attn_window_kernel<<<grid, THREADS>>>(X, W, b, out, length);
}

// round 5
// speedup vs baseline: 3.1647x; 2.7846x over previous
#include <cuda_runtime.h>
#include <cuda_fp16.h>
#include <cstdint>

#define RANK    64
#define WIN     11
#define TILE    128
#define THREADS 256
#define RPW     16
#define NROWS   138      // staged rows; buffer row br <-> global row tile_start + br - 5
#define XSTR    68       // xt row stride in floats (272B)
#define WSTR    68       // W row stride in floats
#define V1STR   68       // v1 row stride in halves (136B)

// byte offsets in dynamic smem
#define XT_OFF  0                       // 138*272 = 37536
#define UN_OFF  37536                   // W fp32 (64*272=17408) then v1 fp16 (128*136=17408)
#define SC_OFF  54944                   // sc[128][13] fp32 = 6656
#define BS_OFF  61600                   // bias 256B
#define SMEM_BYTES 61888

#define FMA2(d, a, b, c) \
    asm("fma.rn.f32x2 %0, %1, %2, %3;" : "=l"(d) : "l"(a), "l"(b), "l"(c))
#define PACKF2(d, x, y) \
    asm("mov.b64 %0, {%1, %2};" : "=l"(d) : "f"(x), "f"(y))

__device__ __forceinline__ float2 unpack2(unsigned long long v) {
    float2 r;
    asm("mov.b64 {%0, %1}, %2;" : "=f"(r.x), "=f"(r.y) : "l"(v));
    return r;
}
__device__ __forceinline__ uint32_t f2tf32(float f) {
    uint32_t u;
    asm("cvt.rna.tf32.f32 %0, %1;" : "=r"(u) : "f"(f));
    return u;
}
// tanh(x) = 1 - 2/(e^(2x)+1), rel err ~1e-5
__device__ __forceinline__ float fast_tanh(float x) {
    float e = __expf(2.0f * x);
    return 1.0f - __fdividef(2.0f, e + 1.0f);
}

#define MMA_TF32(d, a0, a1, a2, a3, b0, b1) \
    asm volatile("mma.sync.aligned.m16n8k8.row.col.f32.tf32.tf32.f32 " \
        "{%0,%1,%2,%3}, {%4,%5,%6,%7}, {%8,%9}, {%0,%1,%2,%3};" \
        : "+f"((d)[0]), "+f"((d)[1]), "+f"((d)[2]), "+f"((d)[3]) \
        : "r"(a0), "r"(a1), "r"(a2), "r"(a3), "r"(b0), "r"(b1))

__global__ void __launch_bounds__(THREADS, 3) attn_window_kernel(
    const float* __restrict__ X,   // (L, 64)
    const float* __restrict__ W,   // (64, 64) row-major (out, in)
    const float* __restrict__ b,   // (64,)
    float* __restrict__ out,       // (L, 64)
    int length)
{
    extern __shared__ __align__(16) char sm[];
    float*  xt  = (float*)(sm + XT_OFF);
    float*  wsm = (float*)(sm + UN_OFF);
    __half* v1h = (__half*)(sm + UN_OFF);   // overlays W after phase A
    float*  scm = (float*)(sm + SC_OFF);
    float*  bsm = (float*)(sm + BS_OFF);

    const int tid  = threadIdx.x;
    const int lane = tid & 31;
    const int wid  = tid >> 5;
    const int gid  = lane >> 2;     // mma group id (0..7)
    const int tg   = lane & 3;      // thread-in-group (0..3)
    const int tile_start = blockIdx.x * TILE;
    const int m0 = wid * RPW;       // warp's first local row

    // ---- stage X: rows tile_start-5 .. tile_start+132, stride 68, zero-padded ----
    #pragma unroll
    for (int i = 0; i < 9; i++) {
        int idx = tid + i * THREADS;            // float4 chunk id
        if (idx < NROWS * 16) {
            int br  = idx >> 4;
            int col = (idx & 15) << 2;
            int gr  = tile_start + br - 5;
            float4 v = make_float4(0.f, 0.f, 0.f, 0.f);
            if (gr >= 0 && gr < length)
                v = *reinterpret_cast<const float4*>(&X[(size_t)gr * RANK + col]);
            *reinterpret_cast<float4*>(&xt[br * XSTR + col]) = v;
        }
    }
    // ---- stage W (64x64) stride 68 ----
    #pragma unroll
    for (int i = 0; i < 4; i++) {
        int idx = tid + i * THREADS;
        int row = idx >> 4;
        int col = (idx & 15) << 2;
        float4 v = *reinterpret_cast<const float4*>(&W[row * RANK + col]);
        *reinterpret_cast<float4*>(&wsm[row * WSTR + col]) = v;
    }
    if (tid < RANK) bsm[tid] = b[tid];
    __syncthreads();

    // ---- Phase A: D(16x64 per warp) = X * W^T via mma.sync tf32 ----
    float acc[8][4];
    #pragma unroll
    for (int j = 0; j < 8; j++)
        #pragma unroll
        for (int q = 0; q < 4; q++) acc[j][q] = 0.f;

    {
        const int r0 = (m0 + 5 + gid) * XSTR;       // A row gid
        const int r1 = r0 + 8 * XSTR;               // A row gid+8
        #pragma unroll
        for (int kk = 0; kk < 8; kk++) {
            const int k0 = kk * 8 + tg;
            uint32_t a0 = f2tf32(xt[r0 + k0]);
            uint32_t a1 = f2tf32(xt[r1 + k0]);
            uint32_t a2 = f2tf32(xt[r0 + k0 + 4]);
            uint32_t a3 = f2tf32(xt[r1 + k0 + 4]);
            #pragma unroll
            for (int j = 0; j < 8; j++) {
                uint32_t b0 = f2tf32(wsm[(8 * j + gid) * WSTR + k0]);
                uint32_t b1 = f2tf32(wsm[(8 * j + gid) * WSTR + k0 + 4]);
                MMA_TF32(acc[j], a0, a1, a2, a3, b0, b1);
            }
        }
    }
    __syncthreads();   // all warps done reading W before v1 overlays it

    // ---- v1 = tanh(D + bias), store fp16 (stride 68 halves) ----
    {
        #pragma unroll
        for (int j = 0; j < 8; j++) {
            const int c = 8 * j + 2 * tg;
            float2 bb = *reinterpret_cast<const float2*>(&bsm[c]);
            __half2 h0 = __floats2half2_rn(fast_tanh(acc[j][0] + bb.x),
                                           fast_tanh(acc[j][1] + bb.y));
            __half2 h1 = __floats2half2_rn(fast_tanh(acc[j][2] + bb.x),
                                           fast_tanh(acc[j][3] + bb.y));
            *reinterpret_cast<__half2*>(&v1h[(m0 + gid) * V1STR + c])     = h0;
            *reinterpret_cast<__half2*>(&v1h[(m0 + gid + 8) * V1STR + c]) = h1;
        }
    }
    __syncwarp();

    // ---- Scores: S'(16x32) = V1 * Xnbr^T via mma.sync tf32 (band kept) ----
    {
        float sac[4][4];
        #pragma unroll
        for (int j = 0; j < 4; j++)
            #pragma unroll
            for (int q = 0; q < 4; q++) sac[j][q] = 0.f;

        const __half* va0 = &v1h[(m0 + gid) * V1STR];
        const __half* va1 = &v1h[(m0 + gid + 8) * V1STR];
        #pragma unroll
        for (int kk = 0; kk < 8; kk++) {
            const int k0 = kk * 8 + tg;
            uint32_t a0 = f2tf32(__half2float(va0[k0]));
            uint32_t a1 = f2tf32(__half2float(va1[k0]));
            uint32_t a2 = f2tf32(__half2float(va0[k0 + 4]));
            uint32_t a3 = f2tf32(__half2float(va1[k0 + 4]));
            #pragma unroll
            for (int j = 0; j < 4; j++) {
                const int br = m0 + 8 * j + gid;       // neighbor buffer row (B col n=8j+gid)
                uint32_t b0 = f2tf32(xt[br * XSTR + k0]);
                uint32_t b1 = f2tf32(xt[br * XSTR + k0 + 4]);
                MMA_TF32(sac[j], a0, a1, a2, a3, b0, b1);
            }
        }
        // banded predicated stores: D'[rr][n], w = n - rr in [0, 11)
        #pragma unroll
        for (int j = 0; j < 4; j++) {
            const int n = 8 * j + 2 * tg;
            const int rA = gid, rB = gid + 8;
            int w;
            w = n     - rA; if (w >= 0 && w < WIN) scm[(m0 + rA) * 13 + w] = sac[j][0];
            w = n + 1 - rA; if (w >= 0 && w < WIN) scm[(m0 + rA) * 13 + w] = sac[j][1];
            w = n     - rB; if (w >= 0 && w < WIN) scm[(m0 + rB) * 13 + w] = sac[j][2];
            w = n + 1 - rB; if (w >= 0 && w < WIN) scm[(m0 + rB) * 13 + w] = sac[j][3];
        }
    }
    __syncthreads();

    // ---- softmax over window per row (threads 0..127), scale 1/8 ----
    if (tid < TILE) {
        float pb[WIN];
        float m = -1e30f;
        #pragma unroll
        for (int w = 0; w < WIN; w++) { pb[w] = scm[tid * 13 + w]; m = fmaxf(m, pb[w]); }
        float s = 0.f;
        #pragma unroll
        for (int w = 0; w < WIN; w++) { pb[w] = __expf((pb[w] - m) * 0.125f); s += pb[w]; }
        float inv = 1.0f / s;
        #pragma unroll
        for (int w = 0; w < WIN; w++) scm[tid * 13 + w] = pb[w] * inv;
    }
    __syncthreads();

    // ---- output: transposed accumulation, 26 x-rows per warp, FMA2 ----
    {
        unsigned long long o[RPW];
        #pragma unroll
        for (int r = 0; r < RPW; r++) o[r] = 0ull;

        #pragma unroll
        for (int t = 0; t < RPW + WIN - 1; t++) {      // buffer rows m0+t
            float2 xv = *reinterpret_cast<const float2*>(&xt[(m0 + t) * XSTR + 2 * lane]);
            unsigned long long xu;
            PACKF2(xu, xv.x, xv.y);
            #pragma unroll
            for (int r = 0; r < RPW; r++) {
                const int w = t - r;
                if (w >= 0 && w < WIN) {
                    float s = scm[(m0 + r) * 13 + w];   // smem broadcast
                    unsigned long long su;
                    PACKF2(su, s, s);
                    FMA2(o[r], su, xu, o[r]);
                }
            }
        }
        #pragma unroll
        for (int r = 0; r < RPW; r++) {
            int gr = tile_start + m0 + r;
            if (gr < length) {
                float2 ov = unpack2(o[r]);
                *reinterpret_cast<float2*>(&out[(size_t)gr * RANK + 2 * lane]) = ov;
            }
        }
    }
}

extern "C" void kernel_launch(void* const* d_in, const int* in_sizes, int n_in,
                              void* d_out, int out_size)
{
    const float* X = (const float*)d_in[0];
    const float* W = (const float*)d_in[1];
    const float* b = (const float*)d_in[2];
    float* out = (float*)d_out;

    const int length = in_sizes[0] / RANK;
    const int grid = (length + TILE - 1) / TILE;
    cudaFuncSetAttribute(attn_window_kernel,
                         cudaFuncAttributeMaxDynamicSharedMemorySize, SMEM_BYTES);
    attn_window_kernel<<<grid, THREADS, SMEM_BYTES>>>(X, W, b, out, length);
}

// round 7
// speedup vs baseline: 4.1108x; 1.2989x over previous
#include <cuda_runtime.h>
#include <cuda_fp16.h>
#include <cstdint>

#define RANK    64
#define WIN     11
#define TILE    128
#define THREADS 256
#define NROWS   144     // staged rows; buffer row br <-> global row tile_start + br - 5
#define XSH     72      // xh row stride in halves (144B, 16B-aligned)
#define V1SH    72      // v1 row stride in halves
#define SPSH    40      // S' row stride in halves (80B, 16B-aligned)

// smem byte offsets
#define XH_OFF   0                    // fp16 X tile: 144*144 = 20736
#define WH_OFF   20736                // fp16 W: 64*144 = 9216 (dead after phase A)
#define SP_OFF   20736                // S' fp16 banded 128*80 = 10240 (overlays W)
#define V1_OFF   30976                // v1 fp16: 128*144 = 18432
#define SCM_OFF  49408                // scm[128][13] fp32 = 6656
#define BS_OFF   56064                // bias fp32, 256B
#define SMEM_BYTES 56320

#define LDSM_X4(r0, r1, r2, r3, a) \
    asm volatile("ldmatrix.sync.aligned.m8n8.x4.shared.b16 {%0,%1,%2,%3}, [%4];" \
        : "=r"(r0), "=r"(r1), "=r"(r2), "=r"(r3) : "r"(a))
#define LDSM_X2T(r0, r1, a) \
    asm volatile("ldmatrix.sync.aligned.m8n8.x2.trans.shared.b16 {%0,%1}, [%2];" \
        : "=r"(r0), "=r"(r1) : "r"(a))
#define HMMA16(d, a0, a1, a2, a3, b0, b1) \
    asm volatile("mma.sync.aligned.m16n8k16.row.col.f32.f16.f16.f32 " \
        "{%0,%1,%2,%3},{%4,%5,%6,%7},{%8,%9},{%0,%1,%2,%3};" \
        : "+f"((d)[0]), "+f"((d)[1]), "+f"((d)[2]), "+f"((d)[3]) \
        : "r"(a0), "r"(a1), "r"(a2), "r"(a3), "r"(b0), "r"(b1))

__device__ __forceinline__ uint32_t sptr(const void* p) {
    return (uint32_t)__cvta_generic_to_shared(p);
}
__device__ __forceinline__ uint32_t h2bits(__half2 h) {
    return *reinterpret_cast<uint32_t*>(&h);
}
// tanh(x) = 1 - 2/(e^(2x)+1), rel err ~1e-5
__device__ __forceinline__ float fast_tanh(float x) {
    float e = __expf(2.0f * x);
    return 1.0f - __fdividef(2.0f, e + 1.0f);
}

__global__ void __launch_bounds__(THREADS) attn_window_kernel(
    const float* __restrict__ X,   // (L, 64)
    const float* __restrict__ W,   // (64, 64) row-major (out, in)
    const float* __restrict__ b,   // (64,)
    float* __restrict__ out,       // (L, 64)
    int length)
{
    extern __shared__ __align__(16) char sm[];
    __half* xh  = (__half*)(sm + XH_OFF);
    __half* wh  = (__half*)(sm + WH_OFF);
    __half* sph = (__half*)(sm + SP_OFF);
    __half* v1h = (__half*)(sm + V1_OFF);
    float*  scm = (float*)(sm + SCM_OFF);
    float*  bsm = (float*)(sm + BS_OFF);

    const int tid  = threadIdx.x;
    const int lane = tid & 31;
    const int wid  = tid >> 5;
    const int gid  = lane >> 2;      // mma group id (0..7)
    const int tg   = lane & 3;       // thread-in-group (0..3)
    const int mat  = lane >> 3;      // ldmatrix matrix id (0..3)
    const int mrow = lane & 7;       // ldmatrix row within matrix
    const int tile_start = blockIdx.x * TILE;
    const int m0 = wid * 16;         // warp's first local row

    // ---- stage X as fp16: 144 rows x 64 halves, zero-padded ----
    #pragma unroll
    for (int i = 0; i < 9; i++) {
        int idx = tid + i * THREADS;            // 0..2303, chunks of 4 floats
        int br  = idx >> 4;
        int col = (idx & 15) << 2;
        int gr  = tile_start + br - 5;
        float4 v = make_float4(0.f, 0.f, 0.f, 0.f);
        if (gr >= 0 && gr < length)
            v = *reinterpret_cast<const float4*>(&X[(size_t)gr * RANK + col]);
        uint2 hv;
        hv.x = h2bits(__floats2half2_rn(v.x, v.y));
        hv.y = h2bits(__floats2half2_rn(v.z, v.w));
        *reinterpret_cast<uint2*>(&xh[br * XSH + col]) = hv;
    }
    // ---- stage W as fp16 ----
    #pragma unroll
    for (int i = 0; i < 4; i++) {
        int idx = tid + i * THREADS;            // 0..1023
        int row = idx >> 4;
        int col = (idx & 15) << 2;
        float4 v = *reinterpret_cast<const float4*>(&W[row * RANK + col]);
        uint2 hv;
        hv.x = h2bits(__floats2half2_rn(v.x, v.y));
        hv.y = h2bits(__floats2half2_rn(v.z, v.w));
        *reinterpret_cast<uint2*>(&wh[row * XSH + col]) = hv;
    }
    if (tid < RANK) bsm[tid] = b[tid];
    __syncthreads();

    // ---- Phase A: D(16x64/warp) = Xtile * W^T, fp16 HMMA, fp32 accum ----
    float acc[8][4];
    #pragma unroll
    for (int j = 0; j < 8; j++)
        #pragma unroll
        for (int q = 0; q < 4; q++) acc[j][q] = 0.f;
    {
        const uint32_t abase = sptr(xh) +
            (uint32_t)(((m0 + 5 + (mat & 1) * 8 + mrow) * XSH + (mat >> 1) * 8) * 2);
        #pragma unroll
        for (int ks = 0; ks < 4; ks++) {
            uint32_t a0, a1, a2, a3;
            LDSM_X4(a0, a1, a2, a3, abase + ks * 32);
            #pragma unroll
            for (int j = 0; j < 8; j++) {
                const __half* wr = &wh[(8 * j + gid) * XSH + ks * 16 + 2 * tg];
                uint32_t b0 = *reinterpret_cast<const uint32_t*>(wr);
                uint32_t b1 = *reinterpret_cast<const uint32_t*>(wr + 8);
                HMMA16(acc[j], a0, a1, a2, a3, b0, b1);
            }
        }
    }
    // ---- v1 = tanh(D + bias) -> fp16 smem ----
    #pragma unroll
    for (int j = 0; j < 8; j++) {
        const int c = 8 * j + 2 * tg;
        float2 bb = *reinterpret_cast<const float2*>(&bsm[c]);
        __half2 h0 = __floats2half2_rn(fast_tanh(acc[j][0] + bb.x),
                                       fast_tanh(acc[j][1] + bb.y));
        __half2 h1 = __floats2half2_rn(fast_tanh(acc[j][2] + bb.x),
                                       fast_tanh(acc[j][3] + bb.y));
        *reinterpret_cast<uint32_t*>(&v1h[(m0 + gid) * V1SH + c])     = h2bits(h0);
        *reinterpret_cast<uint32_t*>(&v1h[(m0 + gid + 8) * V1SH + c]) = h2bits(h1);
    }
    __syncwarp();

    // ---- Scores: S'(16x32) = V1 * Xnbr^T, fp16 HMMA; band kept ----
    {
        float sac[4][4];
        #pragma unroll
        for (int j = 0; j < 4; j++)
            #pragma unroll
            for (int q = 0; q < 4; q++) sac[j][q] = 0.f;

        const uint32_t vbase = sptr(v1h) +
            (uint32_t)(((m0 + (mat & 1) * 8 + mrow) * V1SH + (mat >> 1) * 8) * 2);
        #pragma unroll
        for (int ks = 0; ks < 4; ks++) {
            uint32_t a0, a1, a2, a3;
            LDSM_X4(a0, a1, a2, a3, vbase + ks * 32);
            #pragma unroll
            for (int j = 0; j < 4; j++) {
                const __half* xr = &xh[(m0 + 8 * j + gid) * XSH + ks * 16 + 2 * tg];
                uint32_t b0 = *reinterpret_cast<const uint32_t*>(xr);
                uint32_t b1 = *reinterpret_cast<const uint32_t*>(xr + 8);
                HMMA16(sac[j], a0, a1, a2, a3, b0, b1);
            }
        }
        // banded predicated stores: w = n - r_local in [0, 11)
        #pragma unroll
        for (int j = 0; j < 4; j++) {
            const int n = 8 * j + 2 * tg;
            const int rA = gid, rB = gid + 8;
            int w;
            w = n     - rA; if (w >= 0 && w < WIN) scm[(m0 + rA) * 13 + w] = sac[j][0];
            w = n + 1 - rA; if (w >= 0 && w < WIN) scm[(m0 + rA) * 13 + w] = sac[j][1];
            w = n     - rB; if (w >= 0 && w < WIN) scm[(m0 + rB) * 13 + w] = sac[j][2];
            w = n + 1 - rB; if (w >= 0 && w < WIN) scm[(m0 + rB) * 13 + w] = sac[j][3];
        }
    }
    __syncthreads();

    // ---- softmax over window (threads 0..127, one row each); write banded S' fp16 ----
    if (tid < TILE) {
        float pb[WIN];
        float m = -1e30f;
        #pragma unroll
        for (int w = 0; w < WIN; w++) { pb[w] = scm[tid * 13 + w]; m = fmaxf(m, pb[w]); }
        float s = 0.f;
        #pragma unroll
        for (int w = 0; w < WIN; w++) { pb[w] = __expf((pb[w] - m) * 0.125f); s += pb[w]; }
        float inv = 1.0f / s;
        // FIX: zero the FULL 32-half band row (S' overlays stale W data!), then
        // drop in the 11 probs at n = (tid&15) + w
        uint64_t* rowz = reinterpret_cast<uint64_t*>(&sph[tid * SPSH]);
        #pragma unroll
        for (int q = 0; q < 8; q++) rowz[q] = 0ull;   // 32 halves = 64 bytes
        const int nb = tid & 15;
        #pragma unroll
        for (int w = 0; w < WIN; w++)
            sph[tid * SPSH + nb + w] = __float2half_rn(pb[w] * inv);
    }
    __syncthreads();

    // ---- Output: O(16x64) = S'(16x32) * Xband(32x64), fp16 HMMA ----
    {
        float oac[8][4];
        #pragma unroll
        for (int j = 0; j < 8; j++)
            #pragma unroll
            for (int q = 0; q < 4; q++) oac[j][q] = 0.f;

        const uint32_t pbase = sptr(sph) +
            (uint32_t)(((m0 + (mat & 1) * 8 + mrow) * SPSH + (mat >> 1) * 8) * 2);
        #pragma unroll
        for (int ks = 0; ks < 2; ks++) {
            uint32_t p0, p1, p2, p3;
            LDSM_X4(p0, p1, p2, p3, pbase + ks * 32);
            const uint32_t brow = (uint32_t)(m0 + ks * 16 + ((lane >> 3) & 1) * 8 + mrow);
            #pragma unroll
            for (int j = 0; j < 8; j++) {
                uint32_t baddr = sptr(xh) + (uint32_t)((brow * XSH + 8 * j) * 2);
                uint32_t b0, b1;
                LDSM_X2T(b0, b1, baddr);
                HMMA16(oac[j], p0, p1, p2, p3, b0, b1);
            }
        }
        #pragma unroll
        for (int j = 0; j < 8; j++) {
            const int c = 8 * j + 2 * tg;
            const int gr0 = tile_start + m0 + gid;
            const int gr1 = gr0 + 8;
            if (gr0 < length) {
                float2 v = make_float2(oac[j][0], oac[j][1]);
                *reinterpret_cast<float2*>(&out[(size_t)gr0 * RANK + c]) = v;
            }
            if (gr1 < length) {
                float2 v = make_float2(oac[j][2], oac[j][3]);
                *reinterpret_cast<float2*>(&out[(size_t)gr1 * RANK + c]) = v;
            }
        }
    }
}

extern "C" void kernel_launch(void* const* d_in, const int* in_sizes, int n_in,
                              void* d_out, int out_size)
{
    const float* X = (const float*)d_in[0];
    const float* W = (const float*)d_in[1];
    const float* b = (const float*)d_in[2];
    float* out = (float*)d_out;

    const int length = in_sizes[0] / RANK;
    const int grid = (length + TILE - 1) / TILE;
    cudaFuncSetAttribute(attn_window_kernel,
                         cudaFuncAttributeMaxDynamicSharedMemorySize, SMEM_BYTES);
    attn_window_kernel<<<grid, THREADS, SMEM_BYTES>>>(X, W, b, out, length);
}

// round 8
// speedup vs baseline: 4.4787x; 1.0895x over previous
#include <cuda_runtime.h>
#include <cuda_fp16.h>
#include <cstdint>

#define RANK    64
#define WIN     11
#define TILE    128
#define THREADS 256
#define NROWS   144     // staged rows; buffer row br <-> global row tile_start + br - 5
#define XSH     72      // xh row stride in halves (144B, 16B-aligned)
#define SPSH    40      // S' row stride in halves (80B, 16B-aligned)

// smem byte offsets
#define XH_OFF   0                    // fp16 X tile: 144*144 = 20736
#define WH_OFF   20736                // fp16 W: 64*144 = 9216
#define SP_OFF   29952                // S' fp16 banded: 128*80 = 10240
#define BS_OFF   40192                // bias fp32, 256B
#define SMEM_BYTES 40448

#define LDSM_X4(r0, r1, r2, r3, a) \
    asm volatile("ldmatrix.sync.aligned.m8n8.x4.shared.b16 {%0,%1,%2,%3}, [%4];" \
        : "=r"(r0), "=r"(r1), "=r"(r2), "=r"(r3) : "r"(a))
#define LDSM_X2T(r0, r1, a) \
    asm volatile("ldmatrix.sync.aligned.m8n8.x2.trans.shared.b16 {%0,%1}, [%2];" \
        : "=r"(r0), "=r"(r1) : "r"(a))
#define HMMA16(d, a0, a1, a2, a3, b0, b1) \
    asm volatile("mma.sync.aligned.m16n8k16.row.col.f32.f16.f16.f32 " \
        "{%0,%1,%2,%3},{%4,%5,%6,%7},{%8,%9},{%0,%1,%2,%3};" \
        : "+f"((d)[0]), "+f"((d)[1]), "+f"((d)[2]), "+f"((d)[3]) \
        : "r"(a0), "r"(a1), "r"(a2), "r"(a3), "r"(b0), "r"(b1))

__device__ __forceinline__ uint32_t sptr(const void* p) {
    return (uint32_t)__cvta_generic_to_shared(p);
}
__device__ __forceinline__ uint32_t h2bits(__half2 h) {
    return *reinterpret_cast<uint32_t*>(&h);
}
// tanh(x) = 1 - 2/(e^(2x)+1), rel err ~1e-5
__device__ __forceinline__ float fast_tanh(float x) {
    float e = __expf(2.0f * x);
    return 1.0f - __fdividef(2.0f, e + 1.0f);
}

__global__ void __launch_bounds__(THREADS) attn_window_kernel(
    const float* __restrict__ X,   // (L, 64)
    const float* __restrict__ W,   // (64, 64) row-major (out, in)
    const float* __restrict__ b,   // (64,)
    float* __restrict__ out,       // (L, 64)
    int length)
{
    extern __shared__ __align__(16) char sm[];
    __half* xh  = (__half*)(sm + XH_OFF);
    __half* wh  = (__half*)(sm + WH_OFF);
    __half* sph = (__half*)(sm + SP_OFF);
    float*  bsm = (float*)(sm + BS_OFF);

    const int tid  = threadIdx.x;
    const int lane = tid & 31;
    const int wid  = tid >> 5;
    const int gid  = lane >> 2;      // mma group id (0..7)
    const int tg   = lane & 3;       // thread-in-group (0..3)
    const int mat  = lane >> 3;      // ldmatrix matrix id (0..3)
    const int mrow = lane & 7;       // ldmatrix row within matrix
    const int tile_start = blockIdx.x * TILE;
    const int m0 = wid * 16;         // warp's first local row

    // ---- stage X as fp16: 144 rows x 64 halves, zero-padded ----
    #pragma unroll
    for (int i = 0; i < 9; i++) {
        int idx = tid + i * THREADS;            // 0..2303, chunks of 4 floats
        int br  = idx >> 4;
        int col = (idx & 15) << 2;
        int gr  = tile_start + br - 5;
        float4 v = make_float4(0.f, 0.f, 0.f, 0.f);
        if (gr >= 0 && gr < length)
            v = *reinterpret_cast<const float4*>(&X[(size_t)gr * RANK + col]);
        uint2 hv;
        hv.x = h2bits(__floats2half2_rn(v.x, v.y));
        hv.y = h2bits(__floats2half2_rn(v.z, v.w));
        *reinterpret_cast<uint2*>(&xh[br * XSH + col]) = hv;
    }
    // ---- stage W as fp16 ----
    #pragma unroll
    for (int i = 0; i < 4; i++) {
        int idx = tid + i * THREADS;            // 0..1023
        int row = idx >> 4;
        int col = (idx & 15) << 2;
        float4 v = *reinterpret_cast<const float4*>(&W[row * RANK + col]);
        uint2 hv;
        hv.x = h2bits(__floats2half2_rn(v.x, v.y));
        hv.y = h2bits(__floats2half2_rn(v.z, v.w));
        *reinterpret_cast<uint2*>(&wh[row * XSH + col]) = hv;
    }
    if (tid < RANK) bsm[tid] = b[tid];
    __syncthreads();   // the ONLY block-wide barrier

    // ---- Phase A: D(16x64/warp) = Xtile * W^T, fp16 HMMA, fp32 accum ----
    float acc[8][4];
    #pragma unroll
    for (int j = 0; j < 8; j++)
        #pragma unroll
        for (int q = 0; q < 4; q++) acc[j][q] = 0.f;
    {
        const uint32_t abase = sptr(xh) +
            (uint32_t)(((m0 + 5 + (mat & 1) * 8 + mrow) * XSH + (mat >> 1) * 8) * 2);
        #pragma unroll
        for (int ks = 0; ks < 4; ks++) {
            uint32_t a0, a1, a2, a3;
            LDSM_X4(a0, a1, a2, a3, abase + ks * 32);
            #pragma unroll
            for (int j = 0; j < 8; j++) {
                const __half* wr = &wh[(8 * j + gid) * XSH + ks * 16 + 2 * tg];
                uint32_t b0 = *reinterpret_cast<const uint32_t*>(wr);
                uint32_t b1 = *reinterpret_cast<const uint32_t*>(wr + 8);
                HMMA16(acc[j], a0, a1, a2, a3, b0, b1);
            }
        }
    }

    // ---- v1 = tanh(D + bias), KEPT IN REGISTERS as score A-fragments ----
    // acc[j] cols 8j+2tg+{0,1}: col 16ks+2tg -> j=2ks (a0/a1), col+8 -> j=2ks+1 (a2/a3)
    uint32_t va[8], vb[8];
    #pragma unroll
    for (int j = 0; j < 8; j++) {
        const int c = 8 * j + 2 * tg;
        float2 bb = *reinterpret_cast<const float2*>(&bsm[c]);
        va[j] = h2bits(__floats2half2_rn(fast_tanh(acc[j][0] + bb.x),
                                         fast_tanh(acc[j][1] + bb.y)));
        vb[j] = h2bits(__floats2half2_rn(fast_tanh(acc[j][2] + bb.x),
                                         fast_tanh(acc[j][3] + bb.y)));
    }

    // ---- Scores: S'(16x32) = V1 * Xnbr^T, A straight from registers ----
    float sac[4][4];
    #pragma unroll
    for (int j = 0; j < 4; j++)
        #pragma unroll
        for (int q = 0; q < 4; q++) sac[j][q] = 0.f;
    #pragma unroll
    for (int ks = 0; ks < 4; ks++) {
        #pragma unroll
        for (int j = 0; j < 4; j++) {
            const __half* xr = &xh[(m0 + 8 * j + gid) * XSH + ks * 16 + 2 * tg];
            uint32_t b0 = *reinterpret_cast<const uint32_t*>(xr);
            uint32_t b1 = *reinterpret_cast<const uint32_t*>(xr + 8);
            HMMA16(sac[j], va[2 * ks], vb[2 * ks], va[2 * ks + 1], vb[2 * ks + 1], b0, b1);
        }
    }

    // ---- softmax in registers: row rA=gid and rB=gid+8, quad (tg) reduction ----
    {
        float mA = -1e30f, mB = -1e30f;
        #pragma unroll
        for (int j = 0; j < 4; j++) {
            const int n = 8 * j + 2 * tg;
            if (n     - gid       >= 0 && n     - gid       < WIN) mA = fmaxf(mA, sac[j][0]);
            if (n + 1 - gid       >= 0 && n + 1 - gid       < WIN) mA = fmaxf(mA, sac[j][1]);
            if (n     - (gid + 8) >= 0 && n     - (gid + 8) < WIN) mB = fmaxf(mB, sac[j][2]);
            if (n + 1 - (gid + 8) >= 0 && n + 1 - (gid + 8) < WIN) mB = fmaxf(mB, sac[j][3]);
        }
        mA = fmaxf(mA, __shfl_xor_sync(0xffffffffu, mA, 1));
        mA = fmaxf(mA, __shfl_xor_sync(0xffffffffu, mA, 2));
        mB = fmaxf(mB, __shfl_xor_sync(0xffffffffu, mB, 1));
        mB = fmaxf(mB, __shfl_xor_sync(0xffffffffu, mB, 2));

        float sA = 0.f, sB = 0.f;
        #pragma unroll
        for (int j = 0; j < 4; j++) {
            const int n = 8 * j + 2 * tg;
            sac[j][0] = (n     - gid       >= 0 && n     - gid       < WIN)
                        ? __expf((sac[j][0] - mA) * 0.125f) : 0.f;
            sac[j][1] = (n + 1 - gid       >= 0 && n + 1 - gid       < WIN)
                        ? __expf((sac[j][1] - mA) * 0.125f) : 0.f;
            sac[j][2] = (n     - (gid + 8) >= 0 && n     - (gid + 8) < WIN)
                        ? __expf((sac[j][2] - mB) * 0.125f) : 0.f;
            sac[j][3] = (n + 1 - (gid + 8) >= 0 && n + 1 - (gid + 8) < WIN)
                        ? __expf((sac[j][3] - mB) * 0.125f) : 0.f;
            sA += sac[j][0] + sac[j][1];
            sB += sac[j][2] + sac[j][3];
        }
        sA += __shfl_xor_sync(0xffffffffu, sA, 1);
        sA += __shfl_xor_sync(0xffffffffu, sA, 2);
        sB += __shfl_xor_sync(0xffffffffu, sB, 1);
        sB += __shfl_xor_sync(0xffffffffu, sB, 2);
        const float invA = 1.0f / sA;
        const float invB = 1.0f / sB;

        // banded S' store, every col 0..31 gets an explicit value (prob or 0)
        #pragma unroll
        for (int j = 0; j < 4; j++) {
            const int n = 8 * j + 2 * tg;
            *reinterpret_cast<uint32_t*>(&sph[(m0 + gid) * SPSH + n]) =
                h2bits(__floats2half2_rn(sac[j][0] * invA, sac[j][1] * invA));
            *reinterpret_cast<uint32_t*>(&sph[(m0 + gid + 8) * SPSH + n]) =
                h2bits(__floats2half2_rn(sac[j][2] * invB, sac[j][3] * invB));
        }
    }
    __syncwarp();   // S' rows are warp-private: warp-level visibility suffices

    // ---- Output: O(16x64) = S'(16x32) * Xband(32x64), fp16 HMMA ----
    {
        float oac[8][4];
        #pragma unroll
        for (int j = 0; j < 8; j++)
            #pragma unroll
            for (int q = 0; q < 4; q++) oac[j][q] = 0.f;

        const uint32_t pbase = sptr(sph) +
            (uint32_t)(((m0 + (mat & 1) * 8 + mrow) * SPSH + (mat >> 1) * 8) * 2);
        #pragma unroll
        for (int ks = 0; ks < 2; ks++) {
            uint32_t p0, p1, p2, p3;
            LDSM_X4(p0, p1, p2, p3, pbase + ks * 32);
            const uint32_t brow = (uint32_t)(m0 + ks * 16 + ((lane >> 3) & 1) * 8 + mrow);
            #pragma unroll
            for (int j = 0; j < 8; j++) {
                uint32_t baddr = sptr(xh) + (uint32_t)((brow * XSH + 8 * j) * 2);
                uint32_t b0, b1;
                LDSM_X2T(b0, b1, baddr);
                HMMA16(oac[j], p0, p1, p2, p3, b0, b1);
            }
        }
        #pragma unroll
        for (int j = 0; j < 8; j++) {
            const int c = 8 * j + 2 * tg;
            const int gr0 = tile_start + m0 + gid;
            const int gr1 = gr0 + 8;
            if (gr0 < length) {
                float2 v = make_float2(oac[j][0], oac[j][1]);
                *reinterpret_cast<float2*>(&out[(size_t)gr0 * RANK + c]) = v;
            }
            if (gr1 < length) {
                float2 v = make_float2(oac[j][2], oac[j][3]);
                *reinterpret_cast<float2*>(&out[(size_t)gr1 * RANK + c]) = v;
            }
        }
    }
}

extern "C" void kernel_launch(void* const* d_in, const int* in_sizes, int n_in,
                              void* d_out, int out_size)
{
    const float* X = (const float*)d_in[0];
    const float* W = (const float*)d_in[1];
    const float* b = (const float*)d_in[2];
    float* out = (float*)d_out;

    const int length = in_sizes[0] / RANK;
    const int grid = (length + TILE - 1) / TILE;
    cudaFuncSetAttribute(attn_window_kernel,
                         cudaFuncAttributeMaxDynamicSharedMemorySize, SMEM_BYTES);
    attn_window_kernel<<<grid, THREADS, SMEM_BYTES>>>(X, W, b, out, length);
}